// round 12
// baseline (speedup 1.0000x reference)
#include <cuda_runtime.h>
#include <cuda_bf16.h>

// ---------------------------------------------------------------------------
// ConvTransE scoring, algebraically reduced:
//   score[i] = e_t[i]^T (proj_w @ relu(conv(x_i)+b) + proj_b),  x_i = [h_e ; r_e]
// Linear/zero channels folded into an effective 512x512 matrix; the few
// "uncertain" channels + the p==511 edge go through exact-ReLU correction
// columns of one fused GEMM. Tensor cores via hi/lo bf16 split (3x mma.sync
// m16n8k16), ldmatrix fragments, 4-stage cp.async pipeline in STATIC smem.
// 3 launches total: k1 (gather+zero+max), k3 (fold, writes B transposed+split
// directly), k4 (persistent GEMM). Classification recomputed per-block.
// ---------------------------------------------------------------------------

#define BATCH    2048
#define DIM      512
#define CH       32
#define NMAXPAD  16960

__device__ __align__(16) float g_H[BATCH * DIM];     // gathered h_e rows (fp32, coefs)
__device__ __align__(16) __nv_bfloat16 g_Ah[BATCH * DIM];   // A hi
__device__ __align__(16) __nv_bfloat16 g_Al[BATCH * DIM];   // A lo
__device__ __align__(16) __nv_bfloat16 g_Bth[NMAXPAD * DIM]; // B^T hi  [n][k]
__device__ __align__(16) __nv_bfloat16 g_Btl[NMAXPAD * DIM]; // B^T lo  [n][k]
__device__ float        g_r0[BATCH];               // rel[r[i]][0]
__device__ float        g_bmax[BATCH];             // per-row max|h_e|

#define MMA_BF16(C, A, B0, B1) \
    asm volatile("mma.sync.aligned.m16n8k16.row.col.f32.bf16.bf16.f32 " \
        "{%0,%1,%2,%3},{%4,%5,%6,%7},{%8,%9},{%0,%1,%2,%3};" \
        : "+f"(C[0]), "+f"(C[1]), "+f"(C[2]), "+f"(C[3]) \
        : "r"(A[0]), "r"(A[1]), "r"(A[2]), "r"(A[3]), "r"(B0), "r"(B1))

#define LDSM_X4(d0, d1, d2, d3, addr) \
    asm volatile("ldmatrix.sync.aligned.m8n8.x4.shared.b16 {%0,%1,%2,%3}, [%4];" \
        : "=r"(d0), "=r"(d1), "=r"(d2), "=r"(d3) : "r"(addr))

#define CP_ASYNC_16(dst, src) \
    asm volatile("cp.async.cg.shared.global [%0], [%1], 16;" :: "r"(dst), "l"(src))
#define CP_COMMIT() asm volatile("cp.async.commit_group;")
#define CP_WAIT2()  asm volatile("cp.async.wait_group 2;")
#define CP_WAIT1()  asm volatile("cp.async.wait_group 1;")
#define CP_WAIT0()  asm volatile("cp.async.wait_group 0;")

// hi/lo bf16 split
__device__ __forceinline__ void split_bf16(float v, __nv_bfloat16& hi, __nv_bfloat16& lo) {
    hi = __float2bfloat16(v);
    lo = __float2bfloat16(v - __bfloat162float(hi));
}

// per-block classification: xmax reduce over g_bmax (blockDim=128),
// then every thread computes the uncertain-channel mask redundantly.
// scr: >= 5 floats of smem scratch. Leaves results in registers.
__device__ __forceinline__ void classify_block(
    const float* __restrict__ cw, const float* __restrict__ cb,
    float* scr, unsigned& mask_out, int& N_out)
{
    const int tid = threadIdx.x;
    const int lane = tid & 31, wid = tid >> 5;
    float m = 0.0f;
    #pragma unroll
    for (int j = tid; j < BATCH; j += 128) m = fmaxf(m, g_bmax[j]);
    #pragma unroll
    for (int off = 16; off > 0; off >>= 1)
        m = fmaxf(m, __shfl_xor_sync(0xffffffffu, m, off));
    if (lane == 0) scr[wid] = m;
    __syncthreads();
    float xmax = fmaxf(fmaxf(scr[0], scr[1]), fmaxf(scr[2], scr[3]));
    __syncthreads();                 // scratch free for reuse after this
    unsigned mask = 0;
    #pragma unroll
    for (int c = 0; c < CH; c++) {
        float w0 = cw[c*3], w1 = cw[c*3+1], w2 = cw[c*3+2], b = cb[c];
        float bound = (fabsf(w0) + fabsf(w1) + fabsf(w2)) * xmax;
        if (b < bound && b > -bound) mask |= (1u << c);
    }
    mask_out = mask;
    N_out = 545 + 511 * __popc(mask);
}

// ------------- K1: gather + zero scores + per-row max + A split -------------
__global__ __launch_bounds__(128) void k1_gather(
    const int* __restrict__ h, const int* __restrict__ r, const int* __restrict__ t,
    const float* __restrict__ ent, const float* __restrict__ rel,
    float* __restrict__ out)
{
    int i = blockIdx.x;
    int tid = threadIdx.x;               // 128 threads, one float4 each
    const float4* hs = (const float4*)(ent + (size_t)h[i] * DIM);
    const float4* ts = (const float4*)(ent + (size_t)t[i] * DIM);
    float4 hv = hs[tid];
    float4 tv = ts[tid];
    ((float4*)g_H)[i * 128 + tid] = hv;
    {
        float v[4] = {tv.x, tv.y, tv.z, tv.w};
        size_t base = (size_t)i * DIM + tid * 4;
        #pragma unroll
        for (int j = 0; j < 4; j++) {
            __nv_bfloat16 hi, lo;
            split_bf16(v[j], hi, lo);
            g_Ah[base + j] = hi;
            g_Al[base + j] = lo;
        }
    }
    float m = fmaxf(fmaxf(fabsf(hv.x), fabsf(hv.y)), fmaxf(fabsf(hv.z), fabsf(hv.w)));
    #pragma unroll
    for (int off = 16; off > 0; off >>= 1)
        m = fmaxf(m, __shfl_xor_sync(0xffffffffu, m, off));
    __shared__ float wm[4];
    if ((tid & 31) == 0) wm[tid >> 5] = m;
    __syncthreads();
    if (tid == 0) {
        g_bmax[i] = fmaxf(fmaxf(wm[0], wm[1]), fmaxf(wm[2], wm[3]));
        g_r0[i] = rel[(size_t)r[i] * DIM];
        out[i] = 0.0f;
    }
}

// ------------- K3: fold conv+proj_w -> B, written TRANSPOSED + hi/lo --------
// acc[n] = T0[n+1] + T1[n] + T2[n-1],  Tj[n] = sum_c weff_j[c] * s_c[n].
// 512 blocks (one d-row each) x 4 warps (8 channels each), software-pipelined
// channel loads (next channel prefetched during fold), smem partial merge.
__global__ __launch_bounds__(128) void k3_build(
    const float* __restrict__ pw, const float* __restrict__ pb,
    const float* __restrict__ cw, const float* __restrict__ cb)
{
    __shared__ __align__(16) float sT[3][4][512];    // 24KB partials (warps 1-3)
    __shared__ __align__(16) float4 sweff[CH];
    const int tid  = threadIdx.x;
    const int warp = tid >> 5;
    const int lane = tid & 31;
    const int d    = blockIdx.x;
    const float* prow = pw + (size_t)d * (CH * DIM);
    const int n0 = lane * 16;

    unsigned umask; int Ncols;
    classify_block(cw, cb, (float*)sT, umask, Ncols);
    if (tid < CH) {
        int c = tid;
        float w0 = cw[c*3], w1 = cw[c*3+1], w2 = cw[c*3+2], b = cb[c];
        float xb = (umask >> c) & 1 ? 0.f : 1.f;     // uncertain -> 0
        // zero channels: b <= -bound -> also 0. Recompute cls==1 test:
        // cls==1 iff not uncertain and b >= bound; bound sign test via:
        // (not uncertain) and b>0 implies linear; b<0 implies zero.
        float lin = (!((umask >> c) & 1) && b > 0.0f) ? 1.0f : 0.0f;
        (void)xb;
        sweff[c] = make_float4(w0 * lin, w1 * lin, w2 * lin, b * lin);
    }
    __syncthreads();

    float T0[16], T1[16], T2[16], T3[16];
    #pragma unroll
    for (int j = 0; j < 16; j++) { T0[j]=0.f; T1[j]=0.f; T2[j]=0.f; T3[j]=0.f; }

    const int cbase = warp * 8;
    const float4* cp0 = (const float4*)(prow + cbase * DIM + n0);
    float4 c0 = cp0[0], c1 = cp0[1], c2 = cp0[2], c3 = cp0[3];
    float4 wv = sweff[cbase];

    #pragma unroll
    for (int cc = 0; cc < 8; cc++) {
        const int c = cbase + cc;
        float4 x0, x1, x2, x3, wn_;
        if (cc < 7) {
            const float4* np = (const float4*)(prow + (c + 1) * DIM + n0);
            x0 = np[0]; x1 = np[1]; x2 = np[2]; x3 = np[3];
            wn_ = sweff[c + 1];
        }
        if (lane == 31) {                            // edge col (p==511): s[511]=c3.w
            __nv_bfloat16 hi, lo;
            split_bf16(c3.w, hi, lo);
            g_Bth[(size_t)(513 + c) * DIM + d] = hi;
            g_Btl[(size_t)(513 + c) * DIM + d] = lo;
        }
        float s[16] = {c0.x,c0.y,c0.z,c0.w, c1.x,c1.y,c1.z,c1.w,
                       c2.x,c2.y,c2.z,c2.w, c3.x,c3.y,c3.z,c3.w};
        #pragma unroll
        for (int j = 0; j < 16; j++) {
            T0[j] = fmaf(wv.x, s[j], T0[j]);
            T1[j] = fmaf(wv.y, s[j], T1[j]);
            T2[j] = fmaf(wv.z, s[j], T2[j]);
            T3[j] = fmaf(wv.w, s[j], T3[j]);
        }
        c0 = x0; c1 = x1; c2 = x2; c3 = x3; wv = wn_;
    }

    if (warp > 0) {
        #pragma unroll
        for (int j = 0; j < 16; j++) {
            sT[warp-1][0][n0 + j] = T0[j];
            sT[warp-1][1][n0 + j] = T1[j];
            sT[warp-1][2][n0 + j] = T2[j];
            sT[warp-1][3][n0 + j] = T3[j];
        }
    }
    __syncthreads();
    if (warp == 0) {
        #pragma unroll
        for (int w = 0; w < 3; w++)
            #pragma unroll
            for (int j = 0; j < 16; j++) {
                T0[j] += sT[w][0][n0 + j];
                T1[j] += sT[w][1][n0 + j];
                T2[j] += sT[w][2][n0 + j];
                T3[j] += sT[w][3][n0 + j];
            }
        float t0n = __shfl_down_sync(0xffffffffu, T0[0], 1);   // T0[n0+16]
        float t2p = __shfl_up_sync(0xffffffffu, T2[15], 1);    // T2[n0-1]
        #pragma unroll
        for (int j = 0; j < 16; j++) {
            int n = n0 + j;
            float t0 = (j < 15) ? T0[j + 1] : t0n;
            float t2 = (j > 0) ? T2[j - 1] : t2p;
            float v = 0.0f;
            if (n <= 509) v += t0;
            if (n <= 510) v += T1[j];
            if (n >= 1)   v += t2;
            __nv_bfloat16 hi, lo;
            split_bf16(v, hi, lo);
            g_Bth[(size_t)n * DIM + d] = hi;                   // transposed M column
            g_Btl[(size_t)n * DIM + d] = lo;
        }
        float tsum = 0.0f;
        #pragma unroll
        for (int j = 0; j < 16; j++)
            if (n0 + j <= 510) tsum += T3[j];
        #pragma unroll
        for (int off = 16; off > 0; off >>= 1)
            tsum += __shfl_xor_sync(0xffffffffu, tsum, off);
        if (lane == 0) {
            __nv_bfloat16 hi, lo;
            split_bf16(tsum + pb[d], hi, lo);
            g_Bth[(size_t)512 * DIM + d] = hi;                 // const column
            g_Btl[(size_t)512 * DIM + d] = lo;
        }
    }

    // uncertain-channel correction columns (exact copies, transposed + split)
    const int U = (Ncols - 545) / 511;
    for (int ui = 0; ui < U; ui++) {
        int c = __fns(umask, 0, ui + 1);
        const float* src = prow + c * DIM;
        size_t nbase = 545 + (size_t)ui * 511;
        for (int p = tid; p < 511; p += 128) {
            __nv_bfloat16 hi, lo;
            split_bf16(src[p], hi, lo);
            g_Bth[(nbase + p) * DIM + d] = hi;
            g_Btl[(nbase + p) * DIM + d] = lo;
        }
    }
}

// -------------------- coef(row, col) for the scoring epilogue ---------------
__device__ __forceinline__ float coef_fn(int row, int n, int Ncols, unsigned umask,
                                         const float* __restrict__ cw,
                                         const float* __restrict__ cb)
{
    if (n >= Ncols) return 0.0f;
    if (n < 512)  return g_H[(size_t)row * DIM + n];
    if (n == 512) return 1.0f;
    const float* Hr = &g_H[(size_t)row * DIM];
    if (n < 545) {
        int c = n - 513;
        float v = fmaf(cw[c * 3], Hr[510],
                  fmaf(cw[c * 3 + 1], Hr[511],
                  fmaf(cw[c * 3 + 2], g_r0[row], cb[c])));
        return fmaxf(v, 0.0f);
    }
    int q = n - 545;
    int ui = q / 511;
    int p = q - ui * 511;                // p in [0, 510]
    int c = __fns(umask, 0, ui + 1);
    float xm1 = (p == 0) ? 0.0f : Hr[p - 1];
    float v = fmaf(cw[c * 3], xm1,
              fmaf(cw[c * 3 + 1], Hr[p],
              fmaf(cw[c * 3 + 2], Hr[p + 1], cb[c])));
    return fmaxf(v, 0.0f);
}

// ---------- K4: persistent tensor-core GEMM + fused scoring (grid-stride) ---
// 64(m) x 64(n) tiles, k-tile 16, 4-stage cp.async ring (48KB static smem),
// ldmatrix fragments, rows padded to 24 bf16 (48B stride, conflict-free).
// Stage layout (bf16 elements): AH 0 (64x24), AL 1536, BH 3072, BL 4608.
#define K4_STRIDE 24
#define K4_STAGE  6144

__global__ __launch_bounds__(128) void k4_gemm(
    const float* __restrict__ cw, const float* __restrict__ cb,
    float* __restrict__ out)
{
    __shared__ __align__(16) __nv_bfloat16 smem[4 * K4_STAGE];   // 49,152 B
    const unsigned sbase = (unsigned)__cvta_generic_to_shared(smem);

    unsigned umask; int Ncols;
    classify_block(cw, cb, (float*)smem, umask, Ncols);
    __syncthreads();                     // scratch reads done before cp.async reuse

    const int ntn = (Ncols + 63) >> 6;
    const int total = ntn * 32;          // 32 m-tiles of 64

    const int tid  = threadIdx.x;
    const int lane = tid & 31;
    const int wn   = tid >> 5;           // 0..3 (n 16-offset)
    const int g = lane >> 2;             // 0..7
    const int q = lane & 3;              // 0..3

    const int l_row  = tid >> 1;         // 0..63
    const int l_half = (tid & 1) * 8;    // 0 or 8

    const int a_r = lane & 15;
    const int a_c = (lane >> 4) << 3;
    const int b_r = ((lane >> 4) << 3) + (lane & 7);
    const int b_c = ((lane >> 3) & 1) << 3;

    for (int tl = blockIdx.x; tl < total; tl += gridDim.x) {
        const int n0 = (tl >> 5) * 64;
        const int m0 = (tl & 31) * 64;

        float c_[4][2][4];
        #pragma unroll
        for (int s = 0; s < 4; s++)
            #pragma unroll
            for (int u = 0; u < 2; u++)
                #pragma unroll
                for (int e = 0; e < 4; e++) c_[s][u][e] = 0.0f;

        auto load_stage = [&](int st, int kc) {
            unsigned stb = sbase + (unsigned)(st * K4_STAGE) * 2;
            unsigned dA = stb + (unsigned)(l_row * K4_STRIDE + l_half) * 2;
            CP_ASYNC_16(dA,            g_Ah + (size_t)(m0 + l_row) * DIM + kc + l_half);
            CP_ASYNC_16(dA + 1536 * 2, g_Al + (size_t)(m0 + l_row) * DIM + kc + l_half);
            unsigned dB = stb + (unsigned)(3072 + l_row * K4_STRIDE + l_half) * 2;
            CP_ASYNC_16(dB,            g_Bth + (size_t)(n0 + l_row) * DIM + kc + l_half);
            CP_ASYNC_16(dB + 1536 * 2, g_Btl + (size_t)(n0 + l_row) * DIM + kc + l_half);
        };

        load_stage(0, 0);  CP_COMMIT();
        load_stage(1, 16); CP_COMMIT();
        load_stage(2, 32); CP_COMMIT();

        #pragma unroll 1
        for (int it = 0; it < 32; it++) {
            if (it < 30) { CP_WAIT2(); }
            else if (it == 30) { CP_WAIT1(); }
            else { CP_WAIT0(); }
            __syncthreads();
            if (it < 29) { load_stage((it + 3) & 3, (it + 3) * 16); CP_COMMIT(); }

            unsigned stb = sbase + (unsigned)((it & 3) * K4_STAGE) * 2;
            unsigned afh[4][4], afl[4][4], bh[4], bl[4];
            #pragma unroll
            for (int s = 0; s < 4; s++) {
                int r = s * 16 + a_r;
                unsigned aH = stb + (unsigned)(r * K4_STRIDE + a_c) * 2;
                LDSM_X4(afh[s][0], afh[s][1], afh[s][2], afh[s][3], aH);
                LDSM_X4(afl[s][0], afl[s][1], afl[s][2], afl[s][3], aH + 1536 * 2);
            }
            {
                int r = wn * 16 + b_r;
                unsigned aB = stb + (unsigned)(3072 + r * K4_STRIDE + b_c) * 2;
                LDSM_X4(bh[0], bh[1], bh[2], bh[3], aB);
                LDSM_X4(bl[0], bl[1], bl[2], bl[3], aB + 1536 * 2);
            }
            #pragma unroll
            for (int s = 0; s < 4; s++)
                #pragma unroll
                for (int u = 0; u < 2; u++) {
                    MMA_BF16(c_[s][u], afh[s], bh[2 * u], bh[2 * u + 1]);
                    MMA_BF16(c_[s][u], afh[s], bl[2 * u], bl[2 * u + 1]);
                    MMA_BF16(c_[s][u], afl[s], bh[2 * u], bh[2 * u + 1]);
                }
        }

        // epilogue: coef-weighted reduction, then width-4 shfl + atomicAdd
        #pragma unroll
        for (int s = 0; s < 4; s++) {
            int row0 = m0 + s * 16 + g;
            int row1 = row0 + 8;
            float rs0 = 0.0f, rs1 = 0.0f;
            #pragma unroll
            for (int u = 0; u < 2; u++) {
                int n = n0 + wn * 16 + u * 8 + 2 * q;
                float cf00 = coef_fn(row0, n,     Ncols, umask, cw, cb);
                float cf01 = coef_fn(row0, n + 1, Ncols, umask, cw, cb);
                float cf10 = coef_fn(row1, n,     Ncols, umask, cw, cb);
                float cf11 = coef_fn(row1, n + 1, Ncols, umask, cw, cb);
                rs0 = fmaf(c_[s][u][0], cf00, fmaf(c_[s][u][1], cf01, rs0));
                rs1 = fmaf(c_[s][u][2], cf10, fmaf(c_[s][u][3], cf11, rs1));
            }
            rs0 += __shfl_down_sync(0xffffffffu, rs0, 2, 4);
            rs0 += __shfl_down_sync(0xffffffffu, rs0, 1, 4);
            rs1 += __shfl_down_sync(0xffffffffu, rs1, 2, 4);
            rs1 += __shfl_down_sync(0xffffffffu, rs1, 1, 4);
            if (q == 0) {
                atomicAdd(&out[row0], rs0);
                atomicAdd(&out[row1], rs1);
            }
        }
        __syncthreads();   // smem stage buffers quiesce before next tile
    }
}

// ---------------------------------------------------------------------------
extern "C" void kernel_launch(void* const* d_in, const int* in_sizes, int n_in,
                              void* d_out, int out_size)
{
    const int*   h      = (const int*)  d_in[0];
    const int*   r      = (const int*)  d_in[1];
    const int*   t      = (const int*)  d_in[2];
    const float* ent    = (const float*)d_in[3];
    const float* rel    = (const float*)d_in[4];
    const float* conv_w = (const float*)d_in[5];
    const float* conv_b = (const float*)d_in[6];
    const float* proj_w = (const float*)d_in[7];
    const float* proj_b = (const float*)d_in[8];
    float* out = (float*)d_out;

    k1_gather<<<BATCH, 128>>>(h, r, t, ent, rel, out);
    k3_build<<<512, 128>>>(proj_w, proj_b, conv_w, conv_b);
    k4_gemm<<<296, 128>>>(conv_w, conv_b, out);
}

// round 14
// speedup vs baseline: 1.2995x; 1.2995x over previous
#include <cuda_runtime.h>
#include <cuda_bf16.h>

// ---------------------------------------------------------------------------
// ConvTransE scoring, algebraically reduced:
//   score[i] = e_t[i]^T (proj_w @ relu(conv(x_i)+b) + proj_b),  x_i = [h_e ; r_e]
// Linear/zero channels folded into an effective 512x512 matrix; the few
// "uncertain" channels + the p==511 edge go through exact-ReLU correction
// columns of one fused GEMM. Tensor cores via hi/lo bf16 split (3x mma.sync
// m16n8k16), ldmatrix fragments, cp.async pipelines in STATIC smem.
// K3 streams proj_w through a 3-stage cp.async ring (decoupled MLP).
// ---------------------------------------------------------------------------

#define BATCH    2048
#define DIM      512
#define CH       32
#define LDB      16960          // >= 265*64, float4-aligned row stride of B
#define NMAXPAD  16960

__device__ __align__(16) float g_B[512 * LDB];       // built GEMM B matrix (fp32)
__device__ __align__(16) float g_H[BATCH * DIM];     // gathered h_e rows (fp32, coefs)
__device__ __align__(16) __nv_bfloat16 g_Ah[BATCH * DIM];   // A hi
__device__ __align__(16) __nv_bfloat16 g_Al[BATCH * DIM];   // A lo
__device__ __align__(16) __nv_bfloat16 g_Bth[NMAXPAD * DIM]; // B^T hi  [n][k]
__device__ __align__(16) __nv_bfloat16 g_Btl[NMAXPAD * DIM]; // B^T lo  [n][k]
__device__ float        g_r0[BATCH];               // rel[r[i]][0]
__device__ float        g_bmax[BATCH];             // per-row max|h_e|
__device__ float4       g_weff[CH];                // (w0,w1,w2,b) if linear else 0
__device__ int          g_unc[CH];                 // compact list of uncertain channels
__device__ int          g_uidx[CH];                // channel -> unc index or -1
__device__ int          g_N;                       // runtime #columns = 545 + 511*U

#define MMA_BF16(C, A, B0, B1) \
    asm volatile("mma.sync.aligned.m16n8k16.row.col.f32.bf16.bf16.f32 " \
        "{%0,%1,%2,%3},{%4,%5,%6,%7},{%8,%9},{%0,%1,%2,%3};" \
        : "+f"(C[0]), "+f"(C[1]), "+f"(C[2]), "+f"(C[3]) \
        : "r"(A[0]), "r"(A[1]), "r"(A[2]), "r"(A[3]), "r"(B0), "r"(B1))

#define LDSM_X4(d0, d1, d2, d3, addr) \
    asm volatile("ldmatrix.sync.aligned.m8n8.x4.shared.b16 {%0,%1,%2,%3}, [%4];" \
        : "=r"(d0), "=r"(d1), "=r"(d2), "=r"(d3) : "r"(addr))

#define CP_ASYNC_16(dst, src) \
    asm volatile("cp.async.cg.shared.global [%0], [%1], 16;" :: "r"(dst), "l"(src))
#define CP_COMMIT() asm volatile("cp.async.commit_group;")
#define CP_WAIT2()  asm volatile("cp.async.wait_group 2;")
#define CP_WAIT1()  asm volatile("cp.async.wait_group 1;")
#define CP_WAIT0()  asm volatile("cp.async.wait_group 0;")

__device__ __forceinline__ void split_bf16(float v, __nv_bfloat16& hi, __nv_bfloat16& lo) {
    hi = __float2bfloat16(v);
    lo = __float2bfloat16(v - __bfloat162float(hi));
}

// ------------- K1: gather + zero scores + per-row max + A split -------------
__global__ __launch_bounds__(128) void k1_gather(
    const int* __restrict__ h, const int* __restrict__ r, const int* __restrict__ t,
    const float* __restrict__ ent, const float* __restrict__ rel,
    float* __restrict__ out)
{
    int i = blockIdx.x;
    int tid = threadIdx.x;               // 128 threads, one float4 each
    const float4* hs = (const float4*)(ent + (size_t)h[i] * DIM);
    const float4* ts = (const float4*)(ent + (size_t)t[i] * DIM);
    float4 hv = hs[tid];
    float4 tv = ts[tid];
    ((float4*)g_H)[i * 128 + tid] = hv;
    {
        float v[4] = {tv.x, tv.y, tv.z, tv.w};
        size_t base = (size_t)i * DIM + tid * 4;
        #pragma unroll
        for (int j = 0; j < 4; j++) {
            __nv_bfloat16 hi, lo;
            split_bf16(v[j], hi, lo);
            g_Ah[base + j] = hi;
            g_Al[base + j] = lo;
        }
    }
    float m = fmaxf(fmaxf(fabsf(hv.x), fabsf(hv.y)), fmaxf(fabsf(hv.z), fabsf(hv.w)));
    #pragma unroll
    for (int off = 16; off > 0; off >>= 1)
        m = fmaxf(m, __shfl_xor_sync(0xffffffffu, m, off));
    __shared__ float wm[4];
    if ((tid & 31) == 0) wm[tid >> 5] = m;
    __syncthreads();
    if (tid == 0) {
        g_bmax[i] = fmaxf(fmaxf(wm[0], wm[1]), fmaxf(wm[2], wm[3]));
        g_r0[i] = rel[(size_t)r[i] * DIM];
        out[i] = 0.0f;
    }
}

// ------------- K2: reduce bmax + classify + effective weights ---------------
__global__ __launch_bounds__(128) void k2_classify(
    const float* __restrict__ cw, const float* __restrict__ cb)
{
    __shared__ float sm[4];
    int tid = threadIdx.x;
    float m = 0.0f;
    #pragma unroll
    for (int j = tid; j < BATCH; j += 128) m = fmaxf(m, g_bmax[j]);
    #pragma unroll
    for (int off = 16; off > 0; off >>= 1)
        m = fmaxf(m, __shfl_xor_sync(0xffffffffu, m, off));
    if ((tid & 31) == 0) sm[tid >> 5] = m;
    __syncthreads();
    if (tid < 32) {
        float xmax = fmaxf(fmaxf(sm[0], sm[1]), fmaxf(sm[2], sm[3]));
        int c = tid;
        float w0 = cw[c*3], w1 = cw[c*3+1], w2 = cw[c*3+2], b = cb[c];
        float bound = (fabsf(w0) + fabsf(w1) + fabsf(w2)) * xmax;
        int cls = (b >= bound) ? 1 : ((b <= -bound) ? 0 : 2);
        float lin = (cls == 1) ? 1.0f : 0.0f;
        g_weff[c] = make_float4(w0 * lin, w1 * lin, w2 * lin, b * lin);
        unsigned msk = __ballot_sync(0xffffffffu, cls == 2);
        if (cls == 2) {
            int idx = __popc(msk & ((1u << c) - 1u));
            g_unc[idx] = c;
            g_uidx[c] = idx;
        } else {
            g_uidx[c] = -1;
        }
        if (c == 0) g_N = 545 + 511 * __popc(msk);
    }
}

// ------------- K3: cp.async-streamed fold conv+proj_w -> B ------------------
// 512 blocks x 256 threads, one d-row per block. proj_w row (64KB) streamed
// through a 3-stage x 16KB cp.async ring (4 stage-groups of 8 channels).
// Branchless T-accumulators (thread owns n = 2t, 2t+1); neighbor terms
// resolved once at the end via an smem exchange. Writes fp32 B rows.
#define K3_NSTG 3
__global__ __launch_bounds__(256) void k3_build(
    const float* __restrict__ pw, const float* __restrict__ pb)
{
    __shared__ __align__(16) float stg[K3_NSTG][8 * 512];   // 48KB
    __shared__ float sred[8];
    const int tid = threadIdx.x;
    const int d = blockIdx.x;
    const float* prow = pw + (size_t)d * (CH * DIM);
    const size_t brow = (size_t)d * LDB;
    const unsigned sb0 = (unsigned)__cvta_generic_to_shared(&stg[0][0]);
    const int n0 = tid * 2;

    float T0[2] = {0,0}, T1[2] = {0,0}, T2[2] = {0,0}, T3[2] = {0,0};

    auto issue = [&](int g) {
        unsigned dstb = sb0 + (unsigned)((g % K3_NSTG) * 8 * 512 * 4);
        const float* src = prow + g * 4096;
        #pragma unroll
        for (int j = 0; j < 4; j++)
            CP_ASYNC_16(dstb + (unsigned)(tid + j * 256) * 16, src + (tid + j * 256) * 4);
        CP_COMMIT();
    };
    issue(0); issue(1); issue(2);

    #pragma unroll 1
    for (int g = 0; g < 4; g++) {
        if (g <= 1) { CP_WAIT2(); }
        else if (g == 2) { CP_WAIT1(); }
        else { CP_WAIT0(); }
        __syncthreads();
        const float* buf = &stg[g % K3_NSTG][0];
        #pragma unroll
        for (int cc = 0; cc < 8; cc++) {
            int c = g * 8 + cc;
            float2 s = *(const float2*)&buf[cc * 512 + n0];
            float4 w = g_weff[c];
            T0[0] = fmaf(w.x, s.x, T0[0]); T0[1] = fmaf(w.x, s.y, T0[1]);
            T1[0] = fmaf(w.y, s.x, T1[0]); T1[1] = fmaf(w.y, s.y, T1[1]);
            T2[0] = fmaf(w.z, s.x, T2[0]); T2[1] = fmaf(w.z, s.y, T2[1]);
            T3[0] = fmaf(w.w, s.x, T3[0]); T3[1] = fmaf(w.w, s.y, T3[1]);
            if (tid == 255) g_B[brow + 513 + c] = s.y;     // edge col (p==511)
            int ui = g_uidx[c];
            if (ui >= 0) {                                 // uncertain: exact copy
                size_t base = brow + 545 + (size_t)ui * 511;
                g_B[base + n0] = s.x;
                if (n0 + 1 < 511) g_B[base + n0 + 1] = s.y;
            }
        }
        __syncthreads();                 // reads done before ring reuse
        if (g == 0) issue(3);
    }

    // end merge: acc[n] = T0[n+1] + T1[n] + T2[n-1] via smem exchange
    float* sT = &stg[0][0];              // reuse: 3*512 floats
    sT[n0] = T0[0];        sT[n0 + 1] = T0[1];
    sT[512 + n0] = T1[0];  sT[512 + n0 + 1] = T1[1];
    sT[1024 + n0] = T2[0]; sT[1024 + n0 + 1] = T2[1];
    __syncthreads();
    {
        int na = n0, nb = n0 + 1;
        float acc0 = 0.0f, acc1 = 0.0f;
        if (na <= 509) acc0 += sT[na + 1];
        if (na <= 510) acc0 += sT[512 + na];
        if (na >= 1)   acc0 += sT[1024 + na - 1];
        if (nb <= 509) acc1 += sT[nb + 1];
        if (nb <= 510) acc1 += sT[512 + nb];
        acc1 += sT[1024 + nb - 1];       // nb >= 1 always
        *(float2*)&g_B[brow + n0] = make_float2(acc0, acc1);
    }
    float cp = T3[0] + ((n0 + 1 <= 510) ? T3[1] : 0.0f);
    #pragma unroll
    for (int off = 16; off > 0; off >>= 1)
        cp += __shfl_xor_sync(0xffffffffu, cp, off);
    if ((tid & 31) == 0) sred[tid >> 5] = cp;
    __syncthreads();
    if (tid == 0) {
        float s = 0.0f;
        #pragma unroll
        for (int w = 0; w < 8; w++) s += sred[w];
        g_B[brow + 512] = s + pb[d];     // const column
    }
}

// ---------- K3.5: transpose + hi/lo split B -> Bt[n][k] (grid-stride) -------
__global__ __launch_bounds__(256) void k35_convertB() {
    const int Ncols = g_N;
    const int nt32 = ((Ncols + 63) & ~63) >> 5;   // cover 64-wide k4 tiles
    const int total = nt32 * 16;                  // 16 k-tiles of 32
    __shared__ float tile[32][33];
    int tx = threadIdx.x & 31, ty = threadIdx.x >> 5;   // ty 0..7
    for (int tl = blockIdx.x; tl < total; tl += gridDim.x) {
        int n0 = (tl >> 4) * 32;
        int k0 = (tl & 15) * 32;
        #pragma unroll
        for (int rr = 0; rr < 4; rr++) {
            int kk = ty + rr * 8;
            tile[kk][tx] = g_B[(size_t)(k0 + kk) * LDB + n0 + tx];
        }
        __syncthreads();
        #pragma unroll
        for (int rr = 0; rr < 4; rr++) {
            int nn = ty + rr * 8;
            float v = tile[tx][nn];
            __nv_bfloat16 hv, lv;
            split_bf16(v, hv, lv);
            g_Bth[(size_t)(n0 + nn) * DIM + k0 + tx] = hv;
            g_Btl[(size_t)(n0 + nn) * DIM + k0 + tx] = lv;
        }
        __syncthreads();
    }
}

// -------------------- coef(row, col) for the scoring epilogue ---------------
__device__ __forceinline__ float coef_fn(int row, int n, int Ncols,
                                         const float* __restrict__ cw,
                                         const float* __restrict__ cb)
{
    if (n >= Ncols) return 0.0f;
    if (n < 512)  return g_H[(size_t)row * DIM + n];
    if (n == 512) return 1.0f;
    const float* Hr = &g_H[(size_t)row * DIM];
    if (n < 545) {
        int c = n - 513;
        float v = fmaf(cw[c * 3], Hr[510],
                  fmaf(cw[c * 3 + 1], Hr[511],
                  fmaf(cw[c * 3 + 2], g_r0[row], cb[c])));
        return fmaxf(v, 0.0f);
    }
    int q = n - 545;
    int ui = q / 511;
    int p = q - ui * 511;                // p in [0, 510]
    int c = g_unc[ui];
    float xm1 = (p == 0) ? 0.0f : Hr[p - 1];
    float v = fmaf(cw[c * 3], xm1,
              fmaf(cw[c * 3 + 1], Hr[p],
              fmaf(cw[c * 3 + 2], Hr[p + 1], cb[c])));
    return fmaxf(v, 0.0f);
}

// ---------- K4: persistent tensor-core GEMM + fused scoring (grid-stride) ---
// 64(m) x 64(n) tiles, k-tile 16, 4-stage cp.async ring (48KB static smem),
// ldmatrix fragments, rows padded to 24 bf16 (48B stride, conflict-free).
// Stage layout (bf16 elements): AH 0 (64x24), AL 1536, BH 3072, BL 4608.
#define K4_STRIDE 24
#define K4_STAGE  6144

__global__ __launch_bounds__(128) void k4_gemm(
    const float* __restrict__ cw, const float* __restrict__ cb,
    float* __restrict__ out)
{
    const int Ncols = g_N;
    const int ntn = (Ncols + 63) >> 6;
    const int total = ntn * 32;          // 32 m-tiles of 64

    __shared__ __align__(16) __nv_bfloat16 smem[4 * K4_STAGE];   // 49,152 B
    const unsigned sbase = (unsigned)__cvta_generic_to_shared(smem);

    const int tid  = threadIdx.x;
    const int lane = tid & 31;
    const int wn   = tid >> 5;           // 0..3 (n 16-offset)
    const int g = lane >> 2;             // 0..7
    const int q = lane & 3;              // 0..3

    const int l_row  = tid >> 1;         // 0..63
    const int l_half = (tid & 1) * 8;    // 0 or 8

    const int a_r = lane & 15;
    const int a_c = (lane >> 4) << 3;
    const int b_r = ((lane >> 4) << 3) + (lane & 7);
    const int b_c = ((lane >> 3) & 1) << 3;

    for (int tl = blockIdx.x; tl < total; tl += gridDim.x) {
        const int n0 = (tl >> 5) * 64;
        const int m0 = (tl & 31) * 64;

        float c_[4][2][4];
        #pragma unroll
        for (int s = 0; s < 4; s++)
            #pragma unroll
            for (int u = 0; u < 2; u++)
                #pragma unroll
                for (int e = 0; e < 4; e++) c_[s][u][e] = 0.0f;

        auto load_stage = [&](int st, int kc) {
            unsigned stb = sbase + (unsigned)(st * K4_STAGE) * 2;
            unsigned dA = stb + (unsigned)(l_row * K4_STRIDE + l_half) * 2;
            CP_ASYNC_16(dA,            g_Ah + (size_t)(m0 + l_row) * DIM + kc + l_half);
            CP_ASYNC_16(dA + 1536 * 2, g_Al + (size_t)(m0 + l_row) * DIM + kc + l_half);
            unsigned dB = stb + (unsigned)(3072 + l_row * K4_STRIDE + l_half) * 2;
            CP_ASYNC_16(dB,            g_Bth + (size_t)(n0 + l_row) * DIM + kc + l_half);
            CP_ASYNC_16(dB + 1536 * 2, g_Btl + (size_t)(n0 + l_row) * DIM + kc + l_half);
        };

        load_stage(0, 0);  CP_COMMIT();
        load_stage(1, 16); CP_COMMIT();
        load_stage(2, 32); CP_COMMIT();

        #pragma unroll 1
        for (int it = 0; it < 32; it++) {
            if (it < 30) { CP_WAIT2(); }
            else if (it == 30) { CP_WAIT1(); }
            else { CP_WAIT0(); }
            __syncthreads();
            if (it < 29) { load_stage((it + 3) & 3, (it + 3) * 16); CP_COMMIT(); }

            unsigned stb = sbase + (unsigned)((it & 3) * K4_STAGE) * 2;
            unsigned afh[4][4], afl[4][4], bh[4], bl[4];
            #pragma unroll
            for (int s = 0; s < 4; s++) {
                int r = s * 16 + a_r;
                unsigned aH = stb + (unsigned)(r * K4_STRIDE + a_c) * 2;
                LDSM_X4(afh[s][0], afh[s][1], afh[s][2], afh[s][3], aH);
                LDSM_X4(afl[s][0], afl[s][1], afl[s][2], afl[s][3], aH + 1536 * 2);
            }
            {
                int r = wn * 16 + b_r;
                unsigned aB = stb + (unsigned)(3072 + r * K4_STRIDE + b_c) * 2;
                LDSM_X4(bh[0], bh[1], bh[2], bh[3], aB);
                LDSM_X4(bl[0], bl[1], bl[2], bl[3], aB + 1536 * 2);
            }
            #pragma unroll
            for (int s = 0; s < 4; s++)
                #pragma unroll
                for (int u = 0; u < 2; u++) {
                    MMA_BF16(c_[s][u], afh[s], bh[2 * u], bh[2 * u + 1]);
                    MMA_BF16(c_[s][u], afh[s], bl[2 * u], bl[2 * u + 1]);
                    MMA_BF16(c_[s][u], afl[s], bh[2 * u], bh[2 * u + 1]);
                }
        }

        // epilogue: coef-weighted reduction, then width-4 shfl + atomicAdd
        #pragma unroll
        for (int s = 0; s < 4; s++) {
            int row0 = m0 + s * 16 + g;
            int row1 = row0 + 8;
            float rs0 = 0.0f, rs1 = 0.0f;
            #pragma unroll
            for (int u = 0; u < 2; u++) {
                int n = n0 + wn * 16 + u * 8 + 2 * q;
                float cf00 = coef_fn(row0, n,     Ncols, cw, cb);
                float cf01 = coef_fn(row0, n + 1, Ncols, cw, cb);
                float cf10 = coef_fn(row1, n,     Ncols, cw, cb);
                float cf11 = coef_fn(row1, n + 1, Ncols, cw, cb);
                rs0 = fmaf(c_[s][u][0], cf00, fmaf(c_[s][u][1], cf01, rs0));
                rs1 = fmaf(c_[s][u][2], cf10, fmaf(c_[s][u][3], cf11, rs1));
            }
            rs0 += __shfl_down_sync(0xffffffffu, rs0, 2, 4);
            rs0 += __shfl_down_sync(0xffffffffu, rs0, 1, 4);
            rs1 += __shfl_down_sync(0xffffffffu, rs1, 2, 4);
            rs1 += __shfl_down_sync(0xffffffffu, rs1, 1, 4);
            if (q == 0) {
                atomicAdd(&out[row0], rs0);
                atomicAdd(&out[row1], rs1);
            }
        }
        __syncthreads();   // smem stage buffers quiesce before next tile
    }
}

// ---------------------------------------------------------------------------
extern "C" void kernel_launch(void* const* d_in, const int* in_sizes, int n_in,
                              void* d_out, int out_size)
{
    const int*   h      = (const int*)  d_in[0];
    const int*   r      = (const int*)  d_in[1];
    const int*   t      = (const int*)  d_in[2];
    const float* ent    = (const float*)d_in[3];
    const float* rel    = (const float*)d_in[4];
    const float* conv_w = (const float*)d_in[5];
    const float* conv_b = (const float*)d_in[6];
    const float* proj_w = (const float*)d_in[7];
    const float* proj_b = (const float*)d_in[8];
    float* out = (float*)d_out;

    k1_gather<<<BATCH, 128>>>(h, r, t, ent, rel, out);
    k2_classify<<<1, 128>>>(conv_w, conv_b);
    k3_build<<<512, 256>>>(proj_w, proj_b);
    k35_convertB<<<296, 256>>>();
    k4_gemm<<<296, 128>>>(conv_w, conv_b, out);
}